// round 13
// baseline (speedup 1.0000x reference)
#include <cuda_runtime.h>
#include <cuda_fp16.h>
#include <math.h>
#include <stdint.h>

#define SEQ 4096
#define DIM 1024
#define NH  16
#define HD  64
#define KT  32   // keys per flash tile

// ---------------- device scratch (no allocation allowed) ----------------
__device__ float g_qkv[SEQ * 3 * DIM];     // QKV projection output
__device__ float g_Q[NH * SEQ * HD];       // roped Q, head-major, fp32
__device__ uint4 g_Kh4[NH * SEQ * HD / 8]; // K rounded to fp16, head-major
__device__ uint4 g_Vh4[NH * SEQ * HD / 8]; // V rounded to fp16, head-major
__device__ float g_O[SEQ * DIM];           // attention output (s, dim)
__device__ float g_att[SEQ * DIM];         // after out-proj, pre-LN
__device__ float g_cos[SEQ * 512];
__device__ float g_sin[SEQ * 512];
__device__ float g_invf[512];

// ---------------- FP16 helpers ------------------------------------------
__device__ __forceinline__ void mma_f16(float* c, const unsigned* a, const unsigned* b) {
    asm volatile(
        "mma.sync.aligned.m16n8k16.row.col.f32.f16.f16.f32 "
        "{%0,%1,%2,%3}, {%4,%5,%6,%7}, {%8,%9}, {%0,%1,%2,%3};"
        : "+f"(c[0]), "+f"(c[1]), "+f"(c[2]), "+f"(c[3])
        : "r"(a[0]), "r"(a[1]), "r"(a[2]), "r"(a[3]), "r"(b[0]), "r"(b[1]));
}
// exact hi/lo fp16 split of a pair (consecutive along k)
__device__ __forceinline__ void split_pack_h(float a, float b, unsigned& h, unsigned& l) {
    __half ah = __float2half_rn(a);
    __half bh = __float2half_rn(b);
    float ar = a - __half2float(ah);
    float br = b - __half2float(bh);
    __half2 hv; hv.x = ah; hv.y = bh;
    __half2 lv = __floats2half2_rn(ar, br);
    h = *reinterpret_cast<unsigned*>(&hv);
    l = *reinterpret_cast<unsigned*>(&lv);
}
// round-only fp16 pack of a pair
__device__ __forceinline__ unsigned pack_h(float a, float b) {
    __half2 hv = __floats2half2_rn(a, b);
    return *reinterpret_cast<unsigned*>(&hv);
}
__device__ __forceinline__ void ldsm_x4_trans(unsigned& r0, unsigned& r1,
                                              unsigned& r2, unsigned& r3, unsigned addr) {
    asm volatile("ldmatrix.sync.aligned.m8n8.x4.trans.shared.b16 {%0,%1,%2,%3}, [%4];"
                 : "=r"(r0), "=r"(r1), "=r"(r2), "=r"(r3) : "r"(addr));
}
__device__ __forceinline__ void ldsm_x4(unsigned& r0, unsigned& r1,
                                        unsigned& r2, unsigned& r3, unsigned addr) {
    asm volatile("ldmatrix.sync.aligned.m8n8.x4.shared.b16 {%0,%1,%2,%3}, [%4];"
                 : "=r"(r0), "=r"(r1), "=r"(r2), "=r"(r3) : "r"(addr));
}
__device__ __forceinline__ unsigned smem_u32(const void* p) {
    unsigned a;
    asm("{ .reg .u64 t; cvta.to.shared.u64 t, %1; cvt.u32.u64 %0, t; }" : "=r"(a) : "l"(p));
    return a;
}

// ---------------- RoPE tables -------------------------------------------
__global__ void rope_invf_kernel() {
    int i = blockIdx.x * blockDim.x + threadIdx.x;
    if (i < 512)
        g_invf[i] = (float)exp(-((double)i) * (9.210340371976184 / 512.0));
}
__global__ void rope_tables_kernel() {
    int idx = blockIdx.x * blockDim.x + threadIdx.x;
    if (idx >= SEQ * 512) return;
    int s = idx >> 9;
    int i = idx & 511;
    float ang = (float)s * g_invf[i];
    double a = (double)ang;
    double k = rint(a * 0.15915494309189535);
    float r = (float)(a - k * 6.283185307179586);
    g_cos[idx] = cosf(r);
    g_sin[idx] = sinf(r);
}

// ---------------- RoPE apply + head-major scatter + fp16 round ----------
__global__ void rope_scatter_kernel() {
    int idx = blockIdx.x * blockDim.x + threadIdx.x;   // SEQ*DIM threads
    int s = idx >> 10;
    int j = idx & 1023;
    int i = j & 511;
    float c  = g_cos[(s << 9) + i];
    float sn = g_sin[(s << 9) + i];
    const float* row = g_qkv + (size_t)s * (3 * DIM);
    float q = row[j];
    float k = row[DIM + j];
    float v = row[2 * DIM + j];
    float q2, k2;
    if (j < 512) { q2 = -row[j + 512];       k2 = -row[DIM + j + 512]; }
    else         { q2 =  row[j - 512];       k2 =  row[DIM + j - 512]; }
    float qo = q * c + q2 * sn;
    float ko = k * c + k2 * sn;
    int h = j >> 6, d = j & 63;
    int o = ((h * SEQ) + s) * HD + d;
    g_Q[o] = qo;
    ((__half*)g_Kh4)[o] = __float2half_rn(ko);
    ((__half*)g_Vh4)[o] = __float2half_rn(v);
}

// ---------------- FP16x2 tensor-core GEMM: C = A@B + bias ---------------
// 128x128x32 tile, 256 threads = 8 warps (4m x 2n), warp tile 32x64.
// A split exactly (ah+al), B rounded (bh): acc = ah*bh + al*bh. 64 mmas/chunk.
__device__ __forceinline__
void f16_gemm_bias_body(int N, int K,
                        const float* __restrict__ A,
                        const float* __restrict__ B,
                        const float* __restrict__ bias,
                        float* __restrict__ C) {
    __shared__ unsigned As_h[128][20], As_l[128][20];
    __shared__ unsigned Bs_h[16][136];

    int tid = threadIdx.x;
    int w = tid >> 5, lane = tid & 31;
    int g = lane >> 2, c = lane & 3;
    int m0 = blockIdx.y * 128, n0 = blockIdx.x * 128;
    int wm = w >> 1, wn = w & 1;

    float acc[2][8][4];
#pragma unroll
    for (int mi = 0; mi < 2; mi++)
#pragma unroll
        for (int ni = 0; ni < 8; ni++)
#pragma unroll
            for (int i = 0; i < 4; i++) acc[mi][ni][i] = 0.f;

    int am = tid >> 1, ak0 = (tid & 1) * 16;
    int bkp = tid >> 4, bn8 = (tid & 15) * 8;

    for (int k0 = 0; k0 < K; k0 += 32) {
        const float* Ap = A + (size_t)(m0 + am) * K + k0 + ak0;
#pragma unroll
        for (int q = 0; q < 4; q++) {
            float4 a4 = *(const float4*)(Ap + 4 * q);
            unsigned h0, l0, h1, l1;
            split_pack_h(a4.x, a4.y, h0, l0);
            split_pack_h(a4.z, a4.w, h1, l1);
            int kp = (ak0 >> 1) + 2 * q;
            As_h[am][kp] = h0;     As_l[am][kp] = l0;
            As_h[am][kp + 1] = h1; As_l[am][kp + 1] = l1;
        }
        const float* Bp0 = B + (size_t)(k0 + 2 * bkp) * N + n0 + bn8;
        const float* Bp1 = Bp0 + N;
#pragma unroll
        for (int q = 0; q < 2; q++) {
            float4 b0 = *(const float4*)(Bp0 + 4 * q);
            float4 b1 = *(const float4*)(Bp1 + 4 * q);
            Bs_h[bkp][bn8 + 4 * q + 0] = pack_h(b0.x, b1.x);
            Bs_h[bkp][bn8 + 4 * q + 1] = pack_h(b0.y, b1.y);
            Bs_h[bkp][bn8 + 4 * q + 2] = pack_h(b0.z, b1.z);
            Bs_h[bkp][bn8 + 4 * q + 3] = pack_h(b0.w, b1.w);
        }
        __syncthreads();

#pragma unroll
        for (int kk = 0; kk < 2; kk++) {
            unsigned ah[2][4], al[2][4];
#pragma unroll
            for (int mi = 0; mi < 2; mi++) {
                int rb = wm * 32 + mi * 16;
                ah[mi][0] = As_h[rb + g][kk * 8 + c];
                ah[mi][1] = As_h[rb + g + 8][kk * 8 + c];
                ah[mi][2] = As_h[rb + g][kk * 8 + c + 4];
                ah[mi][3] = As_h[rb + g + 8][kk * 8 + c + 4];
                al[mi][0] = As_l[rb + g][kk * 8 + c];
                al[mi][1] = As_l[rb + g + 8][kk * 8 + c];
                al[mi][2] = As_l[rb + g][kk * 8 + c + 4];
                al[mi][3] = As_l[rb + g + 8][kk * 8 + c + 4];
            }
#pragma unroll
            for (int ni = 0; ni < 8; ni++) {
                int nb = wn * 64 + ni * 8 + g;
                unsigned bh[2];
                bh[0] = Bs_h[kk * 8 + c][nb];
                bh[1] = Bs_h[kk * 8 + c + 4][nb];
#pragma unroll
                for (int mi = 0; mi < 2; mi++) {
                    mma_f16(acc[mi][ni], ah[mi], bh);
                    mma_f16(acc[mi][ni], al[mi], bh);
                }
            }
        }
        __syncthreads();
    }

#pragma unroll
    for (int mi = 0; mi < 2; mi++) {
#pragma unroll
        for (int ni = 0; ni < 8; ni++) {
            int col = n0 + wn * 64 + ni * 8 + 2 * c;
            float2 bb = *(const float2*)(bias + col);
            int row0 = m0 + wm * 32 + mi * 16 + g;
            float2 c0 = make_float2(acc[mi][ni][0] + bb.x, acc[mi][ni][1] + bb.y);
            float2 c1 = make_float2(acc[mi][ni][2] + bb.x, acc[mi][ni][3] + bb.y);
            *(float2*)(C + (size_t)row0 * N + col) = c0;
            *(float2*)(C + (size_t)(row0 + 8) * N + col) = c1;
        }
    }
}

__global__ __launch_bounds__(256, 2)
void f16_gemm_qkv_kernel(const float* __restrict__ x,
                         const float* __restrict__ Wqkv,
                         const float* __restrict__ bqkv) {
    f16_gemm_bias_body(3 * DIM, DIM, x, Wqkv, bqkv, g_qkv);
}

__global__ __launch_bounds__(256, 2)
void f16_gemm_out_kernel(const float* __restrict__ Wo,
                         const float* __restrict__ bo) {
    f16_gemm_bias_body(DIM, DIM, g_O, Wo, bo, g_att);
}

// ---------------- causal flash attention, FP16x2 tensor cores -----------
// Q split exactly (qh+ql), K rounded: S = qh*Kh + ql*Kh.
// P split exactly (ph+pl), V rounded: O += ph*Vh + pl*Vh.
__global__ __launch_bounds__(256, 2)
void flash_f16_kernel() {
    __shared__ __align__(16) __half Kh[KT][72];
    __shared__ __align__(16) __half Vh[KT][72];

    int h = blockIdx.y;
    int m0 = blockIdx.x * 128;
    int tid = threadIdx.x;
    int w = tid >> 5, lane = tid & 31;
    int g = lane >> 2, c = lane & 3;
    int q0w = m0 + w * 16;

    // ---- Q fragments (pre-scaled by 1/8), fp16 hi/lo, in regs ----
    unsigned qh[4][4], ql[4][4];
    {
        const float* Qb = g_Q + ((size_t)h * SEQ + q0w) * HD;
#pragma unroll
        for (int kk = 0; kk < 4; kk++) {
            float2 p0 = *(const float2*)(Qb + (size_t)g * HD + kk * 16 + 2 * c);
            float2 p1 = *(const float2*)(Qb + (size_t)(g + 8) * HD + kk * 16 + 2 * c);
            float2 p2 = *(const float2*)(Qb + (size_t)g * HD + kk * 16 + 2 * c + 8);
            float2 p3 = *(const float2*)(Qb + (size_t)(g + 8) * HD + kk * 16 + 2 * c + 8);
            split_pack_h(p0.x * 0.125f, p0.y * 0.125f, qh[kk][0], ql[kk][0]);
            split_pack_h(p1.x * 0.125f, p1.y * 0.125f, qh[kk][1], ql[kk][1]);
            split_pack_h(p2.x * 0.125f, p2.y * 0.125f, qh[kk][2], ql[kk][2]);
            split_pack_h(p3.x * 0.125f, p3.y * 0.125f, qh[kk][3], ql[kk][3]);
        }
    }

    // ldmatrix lane bases
    int mrow = ((lane >> 4) & 1) * 8 + (lane & 7);   // K (non-trans)
    int mcol = ((lane >> 3) & 1) * 8;
    unsigned kh_base = smem_u32(&Kh[mrow][mcol]);
    unsigned vh_base = smem_u32(&Vh[lane & 15][(lane >> 4) * 8]);

    float o[8][4];
#pragma unroll
    for (int nn = 0; nn < 8; nn++)
#pragma unroll
        for (int i = 0; i < 4; i++) o[nn][i] = 0.f;
    float mrw[2] = {-INFINITY, -INFINITY};
    float lrw[2] = {0.f, 0.f};

    // loader: one uint4 (8 halves) per thread per array; prefetch tile 0
    int key = tid >> 3, dg = tid & 7;
    size_t lbase = ((size_t)h * SEQ + key) * (HD / 8) + dg;
    uint4 pkh = g_Kh4[lbase];
    uint4 pvh = g_Vh4[lbase];

    int nT = (m0 + 128) / KT;
    for (int t = 0; t < nT; t++) {
        int kt0 = t * KT;
        __syncthreads();   // previous tile fully consumed

        *(uint4*)&Kh[key][dg * 8] = pkh;
        *(uint4*)&Vh[key][dg * 8] = pvh;
        __syncthreads();

        if (t + 1 < nT) {   // prefetch next tile into regs
            size_t roff = lbase + (size_t)(kt0 + KT) * (HD / 8);
            pkh = g_Kh4[roff];
            pvh = g_Vh4[roff];
        }

        if (kt0 <= q0w + 15) {   // warp-level causal tile skip
            // ---- S = Q @ K^T (fp16x2) ----
            float s[4][4];
#pragma unroll
            for (int nn = 0; nn < 4; nn++)
#pragma unroll
                for (int i = 0; i < 4; i++) s[nn][i] = 0.f;
#pragma unroll
            for (int kk = 0; kk < 4; kk++) {
#pragma unroll
                for (int q2 = 0; q2 < 2; q2++) {
                    unsigned kh4[4];
                    unsigned off = q2 * (16 * 144) + kk * 32;
                    ldsm_x4(kh4[0], kh4[1], kh4[2], kh4[3], kh_base + off);
                    mma_f16(s[2 * q2],     qh[kk], kh4);
                    mma_f16(s[2 * q2],     ql[kk], kh4);
                    mma_f16(s[2 * q2 + 1], qh[kk], kh4 + 2);
                    mma_f16(s[2 * q2 + 1], ql[kk], kh4 + 2);
                }
            }

            // ---- causal mask + online softmax ----
            float tmax[2] = {-INFINITY, -INFINITY};
#pragma unroll
            for (int nn = 0; nn < 4; nn++) {
#pragma unroll
                for (int i = 0; i < 4; i++) {
                    int qrow = q0w + g + ((i >> 1) << 3);
                    int kcol = kt0 + nn * 8 + 2 * c + (i & 1);
                    if (kcol > qrow) s[nn][i] = -INFINITY;
                    tmax[i >> 1] = fmaxf(tmax[i >> 1], s[nn][i]);
                }
            }
#pragma unroll
            for (int off = 1; off <= 2; off <<= 1) {
                tmax[0] = fmaxf(tmax[0], __shfl_xor_sync(0xffffffffu, tmax[0], off));
                tmax[1] = fmaxf(tmax[1], __shfl_xor_sync(0xffffffffu, tmax[1], off));
            }
            float mnew0 = fmaxf(mrw[0], tmax[0]);
            float mnew1 = fmaxf(mrw[1], tmax[1]);
            float corr0 = __expf(mrw[0] - mnew0);
            float corr1 = __expf(mrw[1] - mnew1);
            mrw[0] = mnew0; mrw[1] = mnew1;

            float rsum[2] = {0.f, 0.f};
#pragma unroll
            for (int nn = 0; nn < 4; nn++) {
#pragma unroll
                for (int i = 0; i < 4; i++) {
                    float p = __expf(s[nn][i] - ((i >> 1) ? mnew1 : mnew0));
                    s[nn][i] = p;
                    rsum[i >> 1] += p;
                }
            }
#pragma unroll
            for (int off = 1; off <= 2; off <<= 1) {
                rsum[0] += __shfl_xor_sync(0xffffffffu, rsum[0], off);
                rsum[1] += __shfl_xor_sync(0xffffffffu, rsum[1], off);
            }
            lrw[0] = lrw[0] * corr0 + rsum[0];
            lrw[1] = lrw[1] * corr1 + rsum[1];
#pragma unroll
            for (int nn = 0; nn < 8; nn++) {
                o[nn][0] *= corr0; o[nn][1] *= corr0;
                o[nn][2] *= corr1; o[nn][3] *= corr1;
            }

            // ---- O += P @ V (fp16x2); C-frag pairs pack directly to A-frag ----
#pragma unroll
            for (int kk = 0; kk < 2; kk++) {
                unsigned ph[4], pl[4];
                split_pack_h(s[2 * kk][0],     s[2 * kk][1],     ph[0], pl[0]);
                split_pack_h(s[2 * kk][2],     s[2 * kk][3],     ph[1], pl[1]);
                split_pack_h(s[2 * kk + 1][0], s[2 * kk + 1][1], ph[2], pl[2]);
                split_pack_h(s[2 * kk + 1][2], s[2 * kk + 1][3], ph[3], pl[3]);
#pragma unroll
                for (int np = 0; np < 4; np++) {
                    unsigned vh4[4];
                    unsigned off = kk * (16 * 144) + np * 32;
                    ldsm_x4_trans(vh4[0], vh4[1], vh4[2], vh4[3], vh_base + off);
                    mma_f16(o[np * 2],     ph, vh4);
                    mma_f16(o[np * 2],     pl, vh4);
                    mma_f16(o[np * 2 + 1], ph, vh4 + 2);
                    mma_f16(o[np * 2 + 1], pl, vh4 + 2);
                }
            }
        }
    }

    // ---- normalize + write O ----
    float inv0 = 1.f / lrw[0];
    float inv1 = 1.f / lrw[1];
#pragma unroll
    for (int nn = 0; nn < 8; nn++) {
        int d = h * HD + nn * 8 + 2 * c;
        float2 r0 = make_float2(o[nn][0] * inv0, o[nn][1] * inv0);
        float2 r1 = make_float2(o[nn][2] * inv1, o[nn][3] * inv1);
        *(float2*)(g_O + (size_t)(q0w + g) * DIM + d) = r0;
        *(float2*)(g_O + (size_t)(q0w + g + 8) * DIM + d) = r1;
    }
}

// ---------------- LayerNorm over last dim (1024) ------------------------
__global__ __launch_bounds__(256)
void layernorm_kernel(const float* __restrict__ gamma,
                      const float* __restrict__ beta,
                      float* __restrict__ Y) {
    int r = blockIdx.x;
    const float* x = g_att + (size_t)r * DIM;
    int tid = threadIdx.x;

    float s = 0.f, s2 = 0.f;
#pragma unroll
    for (int it = 0; it < DIM / 256; it++) {
        float v = x[tid + it * 256];
        s += v;
        s2 += v * v;
    }
#pragma unroll
    for (int off = 16; off; off >>= 1) {
        s  += __shfl_xor_sync(0xffffffffu, s, off);
        s2 += __shfl_xor_sync(0xffffffffu, s2, off);
    }
    __shared__ float ws[8], ws2[8];
    int w = tid >> 5, lane = tid & 31;
    if (lane == 0) { ws[w] = s; ws2[w] = s2; }
    __syncthreads();
    float S1 = 0.f, S2 = 0.f;
#pragma unroll
    for (int i = 0; i < 8; i++) { S1 += ws[i]; S2 += ws2[i]; }

    float mu  = S1 * (1.f / DIM);
    float var = S2 * (1.f / DIM) - mu * mu;
    float inv = rsqrtf(var + 1e-5f);
#pragma unroll
    for (int it = 0; it < DIM / 256; it++) {
        int j = tid + it * 256;
        float v = x[j];
        Y[(size_t)r * DIM + j] = (v - mu) * inv * gamma[j] + beta[j];
    }
}

// ---------------- launch (pure kernel launches, no runtime API) ---------
extern "C" void kernel_launch(void* const* d_in, const int* in_sizes, int n_in,
                              void* d_out, int out_size) {
    const float* x     = (const float*)d_in[0];
    const float* Wqkv  = (const float*)d_in[1];
    const float* bqkv  = (const float*)d_in[2];
    const float* Wo    = (const float*)d_in[3];
    const float* bo    = (const float*)d_in[4];
    const float* gamma = (const float*)d_in[5];
    const float* beta  = (const float*)d_in[6];
    float* out = (float*)d_out;

    rope_invf_kernel<<<2, 256>>>();
    rope_tables_kernel<<<(SEQ * 512) / 256, 256>>>();
    f16_gemm_qkv_kernel<<<dim3(3 * DIM / 128, SEQ / 128), 256>>>(x, Wqkv, bqkv);
    rope_scatter_kernel<<<(SEQ * DIM) / 256, 256>>>();
    flash_f16_kernel<<<dim3(SEQ / 128, NH), 256>>>();
    f16_gemm_out_kernel<<<dim3(DIM / 128, SEQ / 128), 256>>>(Wo, bo);
    layernorm_kernel<<<SEQ, 256>>>(gamma, beta, out);
}